// round 1
// baseline (speedup 1.0000x reference)
#include <cuda_runtime.h>
#include <math_constants.h>

#define BB 256
#define SS 4096
#define HH 128
#define SPLIT 4
#define ROWS_PER_CTA (SS / SPLIT)   // 1024
#define NWARP 8
#define NTHREADS (NWARP * 32)
#define ITERS (ROWS_PER_CTA / NWARP) // 128

// Scratch for split partials: per (batch, split): [M, L, ctx[128]]
__device__ float g_partial[BB * SPLIT * (HH + 2)];

// Accurate tanh built from EX2+RCP approx MUFU ops (rel err ~1e-7, far inside gate).
__device__ __forceinline__ float tanh_fast(float x) {
    float ax = fabsf(x);
    float e  = __expf(-2.0f * ax);              // MUFU.EX2 path
    float r  = __fdividef(1.0f - e, 1.0f + e);  // MUFU.RCP + mul
    return copysignf(r, x);
}

__global__ __launch_bounds__(NTHREADS)
void attn_pass1(const float* __restrict__ x, const float* __restrict__ w) {
    const int blk   = blockIdx.x;
    const int batch = blk / SPLIT;
    const int split = blk % SPLIT;
    const int warp  = threadIdx.x >> 5;
    const int lane  = threadIdx.x & 31;

    // attention weights: 4 per thread, held in registers
    const float4 w4 = __ldg(reinterpret_cast<const float4*>(w) + lane);

    const float* xb = x + (size_t)batch * SS * HH + (size_t)split * ROWS_PER_CTA * HH;

    float m = -CUDART_INF_F;
    float l = 0.0f;
    float accx = 0.0f, accy = 0.0f, accz = 0.0f, accw = 0.0f;

    #pragma unroll 4
    for (int i = 0; i < ITERS; ++i) {
        const int s = warp + i * NWARP;
        const float4 v = __ldg(reinterpret_cast<const float4*>(xb + (size_t)s * HH) + lane);

        // partial score for this thread's 4 h-values
        float p = tanh_fast(v.x) * w4.x;
        p = fmaf(tanh_fast(v.y), w4.y, p);
        p = fmaf(tanh_fast(v.z), w4.z, p);
        p = fmaf(tanh_fast(v.w), w4.w, p);

        // warp reduction -> full score in all lanes
        #pragma unroll
        for (int off = 16; off; off >>= 1)
            p += __shfl_xor_sync(0xffffffffu, p, off);

        // online softmax update
        const float nm   = fmaxf(m, p);
        const float corr = __expf(m - nm);   // 0 on first iter (m = -inf)
        const float e    = __expf(p - nm);
        l    = fmaf(l, corr, e);
        accx = fmaf(accx, corr, e * v.x);
        accy = fmaf(accy, corr, e * v.y);
        accz = fmaf(accz, corr, e * v.z);
        accw = fmaf(accw, corr, e * v.w);
        m = nm;
    }

    // ---- CTA combine across 8 warps ----
    __shared__ float sm_m[NWARP];
    __shared__ float sm_l[NWARP];
    __shared__ float4 sm_acc[NWARP][32];   // [warp][lane] = this thread's 4 h-values

    if (lane == 0) { sm_m[warp] = m; sm_l[warp] = l; }
    sm_acc[warp][lane] = make_float4(accx, accy, accz, accw);
    __syncthreads();

    if (threadIdx.x < HH) {
        const int h = threadIdx.x;
        float M = -CUDART_INF_F;
        #pragma unroll
        for (int ww = 0; ww < NWARP; ++ww) M = fmaxf(M, sm_m[ww]);

        const float* accf = reinterpret_cast<const float*>(sm_acc);
        float L = 0.0f, C = 0.0f;
        #pragma unroll
        for (int ww = 0; ww < NWARP; ++ww) {
            const float c = __expf(sm_m[ww] - M);
            L = fmaf(c, sm_l[ww], L);
            C = fmaf(c, accf[ww * HH + h], C);
        }

        float* out = g_partial + (size_t)blk * (HH + 2);
        if (h == 0) { out[0] = M; out[1] = L; }
        out[2 + h] = C;
    }
}

__global__ __launch_bounds__(HH)
void attn_pass2(float* __restrict__ out) {
    const int batch = blockIdx.x;
    const int h     = threadIdx.x;
    const float* base = g_partial + (size_t)batch * SPLIT * (HH + 2);

    float M = -CUDART_INF_F;
    #pragma unroll
    for (int k = 0; k < SPLIT; ++k)
        M = fmaxf(M, base[(size_t)k * (HH + 2)]);

    float L = 0.0f, C = 0.0f;
    #pragma unroll
    for (int k = 0; k < SPLIT; ++k) {
        const float* pk = base + (size_t)k * (HH + 2);
        const float c = __expf(pk[0] - M);
        L = fmaf(c, pk[1], L);
        C = fmaf(c, pk[2 + h], C);
    }
    out[(size_t)batch * HH + h] = C / L;
}

extern "C" void kernel_launch(void* const* d_in, const int* in_sizes, int n_in,
                              void* d_out, int out_size) {
    const float* x = (const float*)d_in[0];   // [B, S, H] fp32
    const float* w = (const float*)d_in[1];   // [H, 1]    fp32
    float* out = (float*)d_out;               // [B, H]    fp32

    attn_pass1<<<BB * SPLIT, NTHREADS>>>(x, w);
    attn_pass2<<<BB, HH>>>(out);
}

// round 2
// speedup vs baseline: 1.5587x; 1.5587x over previous
#include <cuda_runtime.h>
#include <math_constants.h>

#define BB 256
#define SS 4096
#define HH 128
#define SPLIT 4
#define ROWS_PER_CTA (SS / SPLIT)   // 1024
#define NWARP 8
#define NTHREADS (NWARP * 32)
#define ITERS (ROWS_PER_CTA / NWARP) // 128

// Scratch for split partials: per (batch, split): [M, L, ctx[128]]
__device__ float g_partial[BB * SPLIT * (HH + 2)];

// Hardware tanh approximation (MUFU.TANH, sm_75+): 1 MUFU op per element.
__device__ __forceinline__ float tanh_hw(float x) {
    float y;
    asm("tanh.approx.f32 %0, %1;" : "=f"(y) : "f"(x));
    return y;
}

__global__ __launch_bounds__(NTHREADS)
void attn_pass1(const float* __restrict__ x, const float* __restrict__ w) {
    const int blk   = blockIdx.x;
    const int batch = blk / SPLIT;
    const int split = blk % SPLIT;
    const int warp  = threadIdx.x >> 5;
    const int lane  = threadIdx.x & 31;

    // attention weights: 4 per thread, held in registers
    const float4 w4 = __ldg(reinterpret_cast<const float4*>(w) + lane);

    const float* xb = x + (size_t)batch * SS * HH + (size_t)split * ROWS_PER_CTA * HH;

    float m = -CUDART_INF_F;
    float l = 0.0f;
    float accx = 0.0f, accy = 0.0f, accz = 0.0f, accw = 0.0f;

    #pragma unroll 4
    for (int i = 0; i < ITERS; ++i) {
        const int s = warp + i * NWARP;
        const float4 v = __ldg(reinterpret_cast<const float4*>(xb + (size_t)s * HH) + lane);

        // partial score for this thread's 4 h-values (MUFU.TANH)
        float p = tanh_hw(v.x) * w4.x;
        p = fmaf(tanh_hw(v.y), w4.y, p);
        p = fmaf(tanh_hw(v.z), w4.z, p);
        p = fmaf(tanh_hw(v.w), w4.w, p);

        // warp reduction -> full score in all lanes (p is warp-uniform after)
        #pragma unroll
        for (int off = 16; off; off >>= 1)
            p += __shfl_xor_sync(0xffffffffu, p, off);

        // deferred-rescale online softmax: branch is warp-coherent since p,m
        // are identical across the warp. After warm-up, p <= m nearly always
        // -> steady path is 1 EX2 per row.
        float e;
        if (p <= m) {
            e = __expf(p - m);
        } else {
            const float corr = __expf(m - p);   // 0 on first iter (m = -inf)
            l    *= corr;
            accx *= corr; accy *= corr; accz *= corr; accw *= corr;
            m = p;
            e = 1.0f;
        }
        l   += e;
        accx = fmaf(e, v.x, accx);
        accy = fmaf(e, v.y, accy);
        accz = fmaf(e, v.z, accz);
        accw = fmaf(e, v.w, accw);
    }

    // ---- CTA combine across 8 warps ----
    __shared__ float sm_m[NWARP];
    __shared__ float sm_l[NWARP];
    __shared__ float4 sm_acc[NWARP][32];   // [warp][lane] = this thread's 4 h-values

    if (lane == 0) { sm_m[warp] = m; sm_l[warp] = l; }
    sm_acc[warp][lane] = make_float4(accx, accy, accz, accw);
    __syncthreads();

    if (threadIdx.x < HH) {
        const int h = threadIdx.x;
        float M = -CUDART_INF_F;
        #pragma unroll
        for (int ww = 0; ww < NWARP; ++ww) M = fmaxf(M, sm_m[ww]);

        const float* accf = reinterpret_cast<const float*>(sm_acc);
        float L = 0.0f, C = 0.0f;
        #pragma unroll
        for (int ww = 0; ww < NWARP; ++ww) {
            const float c = __expf(sm_m[ww] - M);
            L = fmaf(c, sm_l[ww], L);
            C = fmaf(c, accf[ww * HH + h], C);
        }

        float* out = g_partial + (size_t)blk * (HH + 2);
        if (h == 0) { out[0] = M; out[1] = L; }
        out[2 + h] = C;
    }
}

__global__ __launch_bounds__(HH)
void attn_pass2(float* __restrict__ out) {
    const int batch = blockIdx.x;
    const int h     = threadIdx.x;
    const float* base = g_partial + (size_t)batch * SPLIT * (HH + 2);

    float M = -CUDART_INF_F;
    #pragma unroll
    for (int k = 0; k < SPLIT; ++k)
        M = fmaxf(M, base[(size_t)k * (HH + 2)]);

    float L = 0.0f, C = 0.0f;
    #pragma unroll
    for (int k = 0; k < SPLIT; ++k) {
        const float* pk = base + (size_t)k * (HH + 2);
        const float c = __expf(pk[0] - M);
        L = fmaf(c, pk[1], L);
        C = fmaf(c, pk[2 + h], C);
    }
    out[(size_t)batch * HH + h] = C / L;
}

extern "C" void kernel_launch(void* const* d_in, const int* in_sizes, int n_in,
                              void* d_out, int out_size) {
    const float* x = (const float*)d_in[0];   // [B, S, H] fp32
    const float* w = (const float*)d_in[1];   // [H, 1]    fp32
    float* out = (float*)d_out;               // [B, H]    fp32

    attn_pass1<<<BB * SPLIT, NTHREADS>>>(x, w);
    attn_pass2<<<BB, HH>>>(out);
}

// round 4
// speedup vs baseline: 1.7192x; 1.1030x over previous
#include <cuda_runtime.h>
#include <math_constants.h>

#define BB 256
#define SS 4096
#define HH 128
#define SPLIT 4
#define ROWS_PER_CTA (SS / SPLIT)    // 1024
#define NWARP 16
#define NTHREADS (NWARP * 32)        // 512
#define ROWS_PER_ITER (NWARP * 2)    // 32 rows per CTA iteration
#define ITERS (ROWS_PER_CTA / ROWS_PER_ITER) // 32

// Scratch for split partials: per (batch, split): [M, L, ctx[128]]
__device__ float g_partial[BB * SPLIT * (HH + 2)];
__device__ int   g_count[BB];   // zero-initialized; reset by last CTA each launch

// Hardware tanh approximation (MUFU.TANH): 1 MUFU op per element.
__device__ __forceinline__ float tanh_hw(float x) {
    float y;
    asm("tanh.approx.f32 %0, %1;" : "=f"(y) : "f"(x));
    return y;
}

__global__ __launch_bounds__(NTHREADS)
void attn_fused(const float* __restrict__ x, const float* __restrict__ w,
                float* __restrict__ out) {
    const int blk   = blockIdx.x;
    const int batch = blk / SPLIT;
    const int split = blk % SPLIT;
    const int warp  = threadIdx.x >> 5;
    const int lane  = threadIdx.x & 31;

    // attention weights: 4 per thread, held in registers
    const float4 w4 = __ldg(reinterpret_cast<const float4*>(w) + lane);

    const float* xb = x + (size_t)batch * SS * HH + (size_t)split * ROWS_PER_CTA * HH;

    float m = -CUDART_INF_F;
    float l = 0.0f;
    float accx = 0.0f, accy = 0.0f, accz = 0.0f, accw = 0.0f;

    #pragma unroll 4
    for (int i = 0; i < ITERS; ++i) {
        // two rows per warp per iteration -> two independent MUFU/SHFL chains
        const int s0 = (warp * 2)     + i * ROWS_PER_ITER;
        const int s1 = (warp * 2 + 1) + i * ROWS_PER_ITER;
        const float4 v0 = __ldg(reinterpret_cast<const float4*>(xb + (size_t)s0 * HH) + lane);
        const float4 v1 = __ldg(reinterpret_cast<const float4*>(xb + (size_t)s1 * HH) + lane);

        float p0 = tanh_hw(v0.x) * w4.x;
        float p1 = tanh_hw(v1.x) * w4.x;
        p0 = fmaf(tanh_hw(v0.y), w4.y, p0);
        p1 = fmaf(tanh_hw(v1.y), w4.y, p1);
        p0 = fmaf(tanh_hw(v0.z), w4.z, p0);
        p1 = fmaf(tanh_hw(v1.z), w4.z, p1);
        p0 = fmaf(tanh_hw(v0.w), w4.w, p0);
        p1 = fmaf(tanh_hw(v1.w), w4.w, p1);

        // two interleaved butterfly reductions (independent chains pipeline)
        #pragma unroll
        for (int off = 16; off; off >>= 1) {
            p0 += __shfl_xor_sync(0xffffffffu, p0, off);
            p1 += __shfl_xor_sync(0xffffffffu, p1, off);
        }

        // deferred-rescale online softmax (warp-coherent branches: p uniform).
        const float pm = fmaxf(p0, p1);
        if (pm > m) {
            const float corr = __expf(m - pm);   // 0 on first iter (m = -inf)
            l    *= corr;
            accx *= corr; accy *= corr; accz *= corr; accw *= corr;
            m = pm;
        }
        const float e0 = __expf(p0 - m);
        const float e1 = __expf(p1 - m);
        l   += e0 + e1;
        accx = fmaf(e0, v0.x, fmaf(e1, v1.x, accx));
        accy = fmaf(e0, v0.y, fmaf(e1, v1.y, accy));
        accz = fmaf(e0, v0.z, fmaf(e1, v1.z, accz));
        accw = fmaf(e0, v0.w, fmaf(e1, v1.w, accw));
    }

    // ---- CTA combine across 16 warps ----
    __shared__ float sm_m[NWARP];
    __shared__ float sm_l[NWARP];
    __shared__ float4 sm_acc[NWARP][32];   // [warp][lane] = this thread's 4 h-values

    if (lane == 0) { sm_m[warp] = m; sm_l[warp] = l; }
    sm_acc[warp][lane] = make_float4(accx, accy, accz, accw);
    __syncthreads();

    if (threadIdx.x < HH) {
        const int h = threadIdx.x;
        float M = -CUDART_INF_F;
        #pragma unroll
        for (int ww = 0; ww < NWARP; ++ww) M = fmaxf(M, sm_m[ww]);

        const float* accf = reinterpret_cast<const float*>(sm_acc);
        float L = 0.0f, C = 0.0f;
        #pragma unroll
        for (int ww = 0; ww < NWARP; ++ww) {
            const float c = __expf(sm_m[ww] - M);
            L = fmaf(c, sm_l[ww], L);
            C = fmaf(c, accf[ww * HH + h], C);
        }

        float* o = g_partial + (size_t)blk * (HH + 2);
        if (h == 0) { o[0] = M; o[1] = L; }
        o[2 + h] = C;
    }

    // ---- last CTA of this batch combines the SPLIT partials (fused pass2) ----
    __shared__ int s_last;
    __syncthreads();
    if (threadIdx.x == 0) {
        __threadfence();   // make this CTA's partial visible before signaling
        const int prev = atomicAdd(&g_count[batch], 1);
        s_last = (prev == SPLIT - 1) ? 1 : 0;
    }
    __syncthreads();

    if (s_last) {
        if (threadIdx.x < HH) {
            const int h = threadIdx.x;
            volatile const float* base =
                g_partial + (size_t)batch * SPLIT * (HH + 2);

            float M = -CUDART_INF_F;
            #pragma unroll
            for (int k = 0; k < SPLIT; ++k)
                M = fmaxf(M, base[(size_t)k * (HH + 2)]);

            float L = 0.0f, C = 0.0f;
            #pragma unroll
            for (int k = 0; k < SPLIT; ++k) {
                volatile const float* pk = base + (size_t)k * (HH + 2);
                const float c = __expf(pk[0] - M);
                L = fmaf(c, pk[1], L);
                C = fmaf(c, pk[2 + h], C);
            }
            out[(size_t)batch * HH + h] = C / L;
        }
        if (threadIdx.x == 0) g_count[batch] = 0;   // reset for next graph replay
    }
}

extern "C" void kernel_launch(void* const* d_in, const int* in_sizes, int n_in,
                              void* d_out, int out_size) {
    const float* x = (const float*)d_in[0];   // [B, S, H] fp32
    const float* w = (const float*)d_in[1];   // [H, 1]    fp32
    float* out = (float*)d_out;               // [B, H]    fp32

    attn_fused<<<BB * SPLIT, NTHREADS>>>(x, w, out);
}